// round 14
// baseline (speedup 1.0000x reference)
#include <cuda_runtime.h>
#include <math_constants.h>

#define NB      32
#define NC      3
#define HH      512
#define WW      512
#define NPATCH  4
#define PSZ     128
#define HALF    64
#define MARGIN  32

// Scratch (no device allocs allowed -> __device__ globals)
__device__ float g_rowval[NB * HH];
__device__ int   g_rowidx[NB * HH];     // flat idx y*W+x of row's first-max
__device__ int   g_coords[NB * NPATCH * 4];

__device__ __forceinline__ void combine(float& bv, int& bi, float v, int i) {
    // first-occurrence argmax: strictly greater wins; tie -> smaller index
    if (v > bv || (v == bv && i < bi)) { bv = v; bi = i; }
}

// ---------------------------------------------------------------------------
// Kernel A: per-row (max, first-argmax) for all B*H rows. One warp per row.
// ---------------------------------------------------------------------------
__global__ void rowmax_init(const float* __restrict__ umap) {
    int w    = blockIdx.x * (blockDim.x >> 5) + (threadIdx.x >> 5);
    int lane = threadIdx.x & 31;
    int b = w >> 9;        // /512
    int y = w & 511;
    const float4* rp = (const float4*)(umap + (size_t)(b * HH + y) * WW);

    float bv = -CUDART_INF_F;
    int   bi = 0x7fffffff;
    #pragma unroll
    for (int i = 0; i < 4; i++) {
        int j = lane + i * 32;          // float4 index within row (0..127)
        float4 v = rp[j];
        int x = j * 4;
        combine(bv, bi, v.x, x);
        combine(bv, bi, v.y, x + 1);
        combine(bv, bi, v.z, x + 2);
        combine(bv, bi, v.w, x + 3);
    }
    #pragma unroll
    for (int off = 16; off; off >>= 1) {
        float ov = __shfl_down_sync(0xffffffffu, bv, off);
        int   oi = __shfl_down_sync(0xffffffffu, bi, off);
        combine(bv, bi, ov, oi);
    }
    if (lane == 0) {
        g_rowval[b * HH + y] = bv;
        g_rowidx[b * HH + y] = y * WW + bi;
    }
}

// ---------------------------------------------------------------------------
// Kernel B: greedy 4-step selection. One CTA (512 thr) per batch image.
// After each pick, re-scan only rows inside the suppression band, testing
// pixels against all boxes selected so far.
// ---------------------------------------------------------------------------
__global__ void select_patches(const float* __restrict__ umap,
                               float* __restrict__ coords_out) {
    int b = blockIdx.x;
    int t = threadIdx.x;

    __shared__ float sval[512];
    __shared__ int   sidx[512];
    __shared__ int   sbx1[NPATCH], sbx2[NPATCH], sby1[NPATCH], sby2[NPATCH];
    __shared__ int   sy1c, sy2c;

    const float* um = umap + (size_t)b * HH * WW;

    for (int it = 0; it < NPATCH; it++) {
        // ---- global argmax over row maxima ----
        sval[t] = g_rowval[b * HH + t];
        sidx[t] = g_rowidx[b * HH + t];
        __syncthreads();
        #pragma unroll
        for (int s = 256; s > 0; s >>= 1) {
            if (t < s) {
                float ov = sval[t + s]; int oi = sidx[t + s];
                float bv = sval[t];     int bi = sidx[t];
                if (ov > bv || (ov == bv && oi < bi)) { sval[t] = ov; sidx[t] = oi; }
            }
            __syncthreads();
        }
        if (t == 0) {
            int idx = sidx[0];
            int yc = idx >> 9;            // /512
            int xc = idx & 511;
            int x1 = min(max(xc - HALF, 0), WW - PSZ);
            int y1 = min(max(yc - HALF, 0), HH - PSZ);
            int x2 = x1 + PSZ, y2 = y1 + PSZ;
            int co = (b * NPATCH + it) * 4;
            g_coords[co + 0] = x1; g_coords[co + 1] = y1;
            coords_out[co + 0] = (float)x1;
            coords_out[co + 1] = (float)y1;
            coords_out[co + 2] = (float)x2;
            coords_out[co + 3] = (float)y2;
            sbx1[it] = x1 - MARGIN; sbx2[it] = x2 + MARGIN;
            sby1[it] = y1 - MARGIN; sby2[it] = y2 + MARGIN;
            sy1c = max(y1 - MARGIN, 0);
            sy2c = min(y2 + MARGIN, HH);
        }
        __syncthreads();
        if (it == NPATCH - 1) break;

        // ---- re-scan rows inside new suppression band, all boxes so far ----
        int wi = t >> 5, lane = t & 31;
        int nb = it + 1;
        for (int y = sy1c + wi; y < sy2c; y += 16) {
            const float4* rp = (const float4*)(um + (size_t)y * WW);
            bool yh[NPATCH];
            #pragma unroll
            for (int k = 0; k < NPATCH; k++)
                yh[k] = (k < nb) && (y >= sby1[k]) && (y < sby2[k]);

            float bv = -CUDART_INF_F;
            int   bi = 0x7fffffff;
            #pragma unroll
            for (int i = 0; i < 4; i++) {
                int j = lane + i * 32;
                float4 v = rp[j];
                int xb = j * 4;
                float e0 = v.x, e1 = v.y, e2 = v.z, e3 = v.w;
                float ev[4] = {e0, e1, e2, e3};
                #pragma unroll
                for (int q = 0; q < 4; q++) {
                    int x = xb + q;
                    bool m = false;
                    #pragma unroll
                    for (int k = 0; k < NPATCH; k++)
                        m = m || (yh[k] && x >= sbx1[k] && x < sbx2[k]);
                    float vv = m ? -CUDART_INF_F : ev[q];
                    combine(bv, bi, vv, x);
                }
            }
            #pragma unroll
            for (int off = 16; off; off >>= 1) {
                float ov = __shfl_down_sync(0xffffffffu, bv, off);
                int   oi = __shfl_down_sync(0xffffffffu, bi, off);
                combine(bv, bi, ov, oi);
            }
            if (lane == 0) {
                g_rowval[b * HH + y] = bv;
                g_rowidx[b * HH + y] = y * WW + bi;
            }
        }
        __syncthreads();   // global writes visible block-wide before next reduce
    }
}

// ---------------------------------------------------------------------------
// Kernel C: extract 128x128 patches. One CTA per (b, n, c).
// ---------------------------------------------------------------------------
__global__ void extract_patches(const float* __restrict__ images,
                                float* __restrict__ out) {
    int bid = blockIdx.x;                     // 0..383
    int b   = bid / (NPATCH * NC);
    int rem = bid % (NPATCH * NC);
    int n   = rem / NC;
    int c   = rem % NC;

    int co = (b * NPATCH + n) * 4;
    int x1 = g_coords[co + 0];
    int y1 = g_coords[co + 1];

    const float* src = images + (((size_t)b * NC + c) * HH + y1) * WW + x1;
    float4* dst = (float4*)(out + ((size_t)(b * NPATCH + n) * NC + c) * PSZ * PSZ);

    const int n4 = PSZ * PSZ / 4;             // 4096 float4
    if ((x1 & 3) == 0) {
        const float4* sp = (const float4*)src;
        for (int i = threadIdx.x; i < n4; i += blockDim.x) {
            int row  = i >> 5;                // 32 float4 per patch row
            int col4 = i & 31;
            dst[i] = sp[row * (WW / 4) + col4];
        }
    } else {
        for (int i = threadIdx.x; i < n4; i += blockDim.x) {
            int row = i >> 5;
            int col = (i & 31) * 4;
            const float* s = src + row * WW + col;
            dst[i] = make_float4(s[0], s[1], s[2], s[3]);
        }
    }
}

// ---------------------------------------------------------------------------
extern "C" void kernel_launch(void* const* d_in, const int* in_sizes, int n_in,
                              void* d_out, int out_size) {
    const float* images = (const float*)d_in[0];
    const float* umaps  = (const float*)d_in[1];
    // robustness: images has 25,165,824 elems, umaps 8,388,608
    if (n_in >= 2 && in_sizes[0] < in_sizes[1]) {
        images = (const float*)d_in[1];
        umaps  = (const float*)d_in[0];
    }

    float* patches = (float*)d_out;
    float* coords  = (float*)d_out + (out_size - NB * NPATCH * 4);

    rowmax_init   <<<NB * HH / 8, 256>>>(umaps);
    select_patches<<<NB, 512>>>(umaps, coords);
    extract_patches<<<NB * NPATCH * NC, 256>>>(images, patches);
}

// round 15
// speedup vs baseline: 2.7420x; 2.7420x over previous
#include <cuda_runtime.h>
#include <math_constants.h>

#define NB      32
#define NC      3
#define HH      512
#define WW      512
#define NPATCH  4
#define PSZ     128
#define HALF    64
#define MARGIN  32

typedef unsigned long long u64;

// Scratch (__device__ globals; allocs forbidden)
__device__ u64 g_rowkey[2][NB * HH];        // packed (valbits<<32)|~flatidx, double-buffered
__device__ int g_coords[NB * NPATCH * 2];   // (x1, y1) per (b, n)
__device__ int g_box[NB * NPATCH * 4];      // suppression boxes with margin: x1m,y1m,x2m,y2m

__device__ __forceinline__ u64 umax64(u64 a, u64 b) { return a > b ? a : b; }

__device__ __forceinline__ u64 pack_key(float v, int flat) {
    // v >= 0 always (uniform [0,1) or fmax thereof) -> bit order == value order
    return ((u64)__float_as_uint(v) << 32) | (unsigned)(~flat);
}

// ---------------------------------------------------------------------------
// Kernel A: per-row packed argmax key for all B*H rows. One warp per row.
// Value reduce via fmaxf tree (parallel), index via equality + min reduce.
// ---------------------------------------------------------------------------
__global__ void rowkey_init(const float* __restrict__ umap) {
    int w    = blockIdx.x * 8 + (threadIdx.x >> 5);
    int lane = threadIdx.x & 31;
    int b = w >> 9;
    int y = w & 511;
    const float4* rp = (const float4*)(umap + (size_t)(b * HH + y) * WW);

    float v[16];
    #pragma unroll
    for (int i = 0; i < 4; i++) {
        float4 f = rp[lane + i * 32];
        v[i * 4 + 0] = f.x; v[i * 4 + 1] = f.y;
        v[i * 4 + 2] = f.z; v[i * 4 + 3] = f.w;
    }
    // tree max (log depth)
    float m8[8], m4[4], m2[2], m;
    #pragma unroll
    for (int i = 0; i < 8; i++) m8[i] = fmaxf(v[i], v[i + 8]);
    #pragma unroll
    for (int i = 0; i < 4; i++) m4[i] = fmaxf(m8[i], m8[i + 4]);
    m2[0] = fmaxf(m4[0], m4[2]); m2[1] = fmaxf(m4[1], m4[3]);
    m = fmaxf(m2[0], m2[1]);
    #pragma unroll
    for (int o = 16; o; o >>= 1) m = fmaxf(m, __shfl_xor_sync(0xffffffffu, m, o));

    // first index equal to max
    int lmin = 0x7fffffff;
    #pragma unroll
    for (int i = 0; i < 4; i++)
        #pragma unroll
        for (int q = 0; q < 4; q++) {
            int x = (lane + i * 32) * 4 + q;
            if (v[i * 4 + q] == m) lmin = min(lmin, x);
        }
    #pragma unroll
    for (int o = 16; o; o >>= 1) lmin = min(lmin, __shfl_xor_sync(0xffffffffu, lmin, o));

    if (lane == 0)
        g_rowkey[0][b * HH + y] = pack_key(m, y * WW + lmin);
}

// ---------------------------------------------------------------------------
// Fused step kernel: every CTA redundantly reduces the 512 row keys (read
// buffer rp -> identical pick in all CTAs), then the grid.y=24 CTAs per batch
// rescan the suppression band into buffer rp^1; non-band rows are copied.
// ---------------------------------------------------------------------------
__global__ void step_kernel(int step, int rp,
                            const float* __restrict__ umap,
                            float* __restrict__ coords_out) {
    int b = blockIdx.x;
    int t = threadIdx.x;

    __shared__ u64 sk[256];
    __shared__ int sbox[NPATCH][4];
    __shared__ int s_band[2];

    if (t < step * 4)
        (&sbox[0][0])[t] = g_box[b * NPATCH * 4 + t];

    const u64* rk = g_rowkey[rp]     + b * HH;
    u64*       wk = g_rowkey[rp ^ 1] + b * HH;

    // ---- argmax over 512 row keys ----
    u64 k = umax64(rk[t], rk[t + 256]);
    sk[t] = k; __syncthreads();
    if (t < 128) sk[t] = umax64(sk[t], sk[t + 128]);
    __syncthreads();
    if (t < 64)  sk[t] = umax64(sk[t], sk[t + 64]);
    __syncthreads();
    if (t < 32) {
        k = umax64(sk[t], sk[t + 32]);
        #pragma unroll
        for (int o = 16; o; o >>= 1) k = umax64(k, __shfl_down_sync(0xffffffffu, k, o));
        if (t == 0) {
            unsigned flat = ~(unsigned)k;
            int yc = (flat >> 9) & 511;
            int xc = flat & 511;
            int x1 = min(max(xc - HALF, 0), WW - PSZ);
            int y1 = min(max(yc - HALF, 0), HH - PSZ);
            sbox[step][0] = x1 - MARGIN; sbox[step][1] = y1 - MARGIN;
            sbox[step][2] = x1 + PSZ + MARGIN; sbox[step][3] = y1 + PSZ + MARGIN;
            s_band[0] = max(y1 - MARGIN, 0);
            s_band[1] = min(y1 + PSZ + MARGIN, HH);
            if (blockIdx.y == 0) {
                g_coords[(b * NPATCH + step) * 2 + 0] = x1;
                g_coords[(b * NPATCH + step) * 2 + 1] = y1;
                int bo = (b * NPATCH + step) * 4;
                g_box[bo + 0] = x1 - MARGIN; g_box[bo + 1] = y1 - MARGIN;
                g_box[bo + 2] = x1 + PSZ + MARGIN; g_box[bo + 3] = y1 + PSZ + MARGIN;
                coords_out[bo + 0] = (float)x1;
                coords_out[bo + 1] = (float)y1;
                coords_out[bo + 2] = (float)(x1 + PSZ);
                coords_out[bo + 3] = (float)(y1 + PSZ);
            }
        }
    }
    __syncthreads();
    int y1c = s_band[0], y2c = s_band[1];

    // ---- copy non-band rows (exact ownership: CTA j owns rows [22j, 22j+22)) ----
    {
        int r = blockIdx.y * 22 + t;
        if (t < 22 && r < HH && (r < y1c || r >= y2c))
            wk[r] = rk[r];
    }

    // ---- rescan band rows: warp per row, 24 CTAs x 8 warps = 192 slots ----
    int wi = t >> 5, lane = t & 31;
    int y = y1c + blockIdx.y * 8 + wi;
    if (y >= y2c) return;

    int nb = step + 1;
    bool yh[NPATCH];
    #pragma unroll
    for (int kk = 0; kk < NPATCH; kk++)
        yh[kk] = (kk < nb) && (y >= sbox[kk][1]) && (y < sbox[kk][3]);

    const float4* rpx = (const float4*)(umap + (size_t)(b * HH + y) * WW);
    float v[16];
    #pragma unroll
    for (int i = 0; i < 4; i++) {
        float4 f = rpx[lane + i * 32];
        float e[4] = {f.x, f.y, f.z, f.w};
        #pragma unroll
        for (int q = 0; q < 4; q++) {
            int x = (lane + i * 32) * 4 + q;
            bool msk = false;
            #pragma unroll
            for (int kk = 0; kk < NPATCH; kk++)
                msk = msk || (yh[kk] && x >= sbox[kk][0] && x < sbox[kk][2]);
            v[i * 4 + q] = msk ? -CUDART_INF_F : e[q];
        }
    }
    float m8[8], m4[4], m;
    #pragma unroll
    for (int i = 0; i < 8; i++) m8[i] = fmaxf(v[i], v[i + 8]);
    #pragma unroll
    for (int i = 0; i < 4; i++) m4[i] = fmaxf(m8[i], m8[i + 4]);
    m = fmaxf(fmaxf(m4[0], m4[2]), fmaxf(m4[1], m4[3]));
    #pragma unroll
    for (int o = 16; o; o >>= 1) m = fmaxf(m, __shfl_xor_sync(0xffffffffu, m, o));

    int lmin = 0x7fffffff;
    #pragma unroll
    for (int i = 0; i < 4; i++)
        #pragma unroll
        for (int q = 0; q < 4; q++) {
            int x = (lane + i * 32) * 4 + q;
            if (v[i * 4 + q] == m) lmin = min(lmin, x);
        }
    #pragma unroll
    for (int o = 16; o; o >>= 1) lmin = min(lmin, __shfl_xor_sync(0xffffffffu, lmin, o));

    if (lane == 0)
        wk[y] = (m < 0.0f) ? 0ull : pack_key(m, y * WW + lmin);
}

// ---------------------------------------------------------------------------
// Extract: one CTA per (b, n, c). CTAs with n==3 compute the final argmax
// themselves from buffer 1 (read-only, deterministic), c==0 writes coords.
// ---------------------------------------------------------------------------
__global__ void extract_patches(const float* __restrict__ images,
                                float* __restrict__ out,
                                float* __restrict__ coords_out) {
    int bid = blockIdx.x;
    int b   = bid / (NPATCH * NC);
    int rem = bid % (NPATCH * NC);
    int n   = rem / NC;
    int c   = rem % NC;
    int t   = threadIdx.x;

    __shared__ int sxy[2];

    if (n == NPATCH - 1) {
        __shared__ u64 sk[256];
        const u64* rk = g_rowkey[1] + b * HH;
        u64 k = umax64(rk[t], rk[t + 256]);
        sk[t] = k; __syncthreads();
        if (t < 128) sk[t] = umax64(sk[t], sk[t + 128]);
        __syncthreads();
        if (t < 64)  sk[t] = umax64(sk[t], sk[t + 64]);
        __syncthreads();
        if (t < 32) {
            k = umax64(sk[t], sk[t + 32]);
            #pragma unroll
            for (int o = 16; o; o >>= 1) k = umax64(k, __shfl_down_sync(0xffffffffu, k, o));
            if (t == 0) {
                unsigned flat = ~(unsigned)k;
                int yc = (flat >> 9) & 511;
                int xc = flat & 511;
                int x1 = min(max(xc - HALF, 0), WW - PSZ);
                int y1 = min(max(yc - HALF, 0), HH - PSZ);
                sxy[0] = x1; sxy[1] = y1;
                if (c == 0) {
                    int co = (b * NPATCH + 3) * 4;
                    coords_out[co + 0] = (float)x1;
                    coords_out[co + 1] = (float)y1;
                    coords_out[co + 2] = (float)(x1 + PSZ);
                    coords_out[co + 3] = (float)(y1 + PSZ);
                }
            }
        }
        __syncthreads();
    } else {
        if (t == 0) {
            sxy[0] = g_coords[(b * NPATCH + n) * 2 + 0];
            sxy[1] = g_coords[(b * NPATCH + n) * 2 + 1];
        }
        __syncthreads();
    }
    int x1 = sxy[0], y1 = sxy[1];

    const float* src = images + (((size_t)b * NC + c) * HH + y1) * WW + x1;
    float4* dst = (float4*)(out + ((size_t)(b * NPATCH + n) * NC + c) * PSZ * PSZ);

    const int n4 = PSZ * PSZ / 4;   // 4096 float4
    if ((x1 & 3) == 0) {
        const float4* sp = (const float4*)src;
        for (int i = t; i < n4; i += blockDim.x) {
            int row  = i >> 5;
            int col4 = i & 31;
            dst[i] = sp[row * (WW / 4) + col4];
        }
    } else {
        for (int i = t; i < n4; i += blockDim.x) {
            int row = i >> 5;
            int col = (i & 31) * 4;
            const float* s = src + row * WW + col;
            dst[i] = make_float4(s[0], s[1], s[2], s[3]);
        }
    }
}

// ---------------------------------------------------------------------------
extern "C" void kernel_launch(void* const* d_in, const int* in_sizes, int n_in,
                              void* d_out, int out_size) {
    const float* images = (const float*)d_in[0];
    const float* umaps  = (const float*)d_in[1];
    if (n_in >= 2 && in_sizes[0] < in_sizes[1]) {
        images = (const float*)d_in[1];
        umaps  = (const float*)d_in[0];
    }

    float* patches = (float*)d_out;
    float* coords  = (float*)d_out + (out_size - NB * NPATCH * 4);

    rowkey_init<<<NB * HH / 8, 256>>>(umaps);
    step_kernel<<<dim3(NB, 24), 256>>>(0, 0, umaps, coords);   // read buf0 -> write buf1
    step_kernel<<<dim3(NB, 24), 256>>>(1, 1, umaps, coords);   // read buf1 -> write buf0
    step_kernel<<<dim3(NB, 24), 256>>>(2, 0, umaps, coords);   // read buf0 -> write buf1
    extract_patches<<<NB * NPATCH * NC, 256>>>(images, patches, coords);  // step3 pick from buf1
}